// round 3
// baseline (speedup 1.0000x reference)
#include <cuda_runtime.h>
#include <cuda_bf16.h>
#include <cstdint>

// Image is 2048 x 2048 float32.
#define IMG_H 2048
#define IMG_W 2048
#define NW 32            // u64 words per row (2048 bits)

typedef unsigned long long u64;

__device__ u64 d_S [IMG_H * NW];   // original strong bits (x > high)
__device__ u64 d_W [IMG_H * NW];   // weak bits (low<=x<=high) & interior-column
__device__ u64 d_So[IMG_H * NW];   // new strong bits after hysteresis (rows 1..2046)
__device__ unsigned d_maxbits;

// ---------------- K0: reset ----------------
__global__ void k0_reset() { d_maxbits = 0u; }

// ---------------- K1: max reduction ----------------
__global__ void k1_max(const float* __restrict__ img) {
    const float4* p4 = reinterpret_cast<const float4*>(img);
    const int n4 = (IMG_H * IMG_W) / 4;
    float m = 0.0f;
    for (int i = blockIdx.x * blockDim.x + threadIdx.x; i < n4;
         i += gridDim.x * blockDim.x) {
        float4 v = p4[i];
        m = fmaxf(m, fmaxf(fmaxf(v.x, v.y), fmaxf(v.z, v.w)));
    }
    // warp reduce
    for (int o = 16; o > 0; o >>= 1)
        m = fmaxf(m, __shfl_xor_sync(0xffffffffu, m, o));
    __shared__ float sm[32];
    int lane = threadIdx.x & 31, wid = threadIdx.x >> 5;
    if (lane == 0) sm[wid] = m;
    __syncthreads();
    if (wid == 0) {
        int nwarp = blockDim.x >> 5;
        m = (lane < nwarp) ? sm[lane] : 0.0f;
        for (int o = 16; o > 0; o >>= 1)
            m = fmaxf(m, __shfl_xor_sync(0xffffffffu, m, o));
        if (lane == 0)
            atomicMax(reinterpret_cast<int*>(&d_maxbits), __float_as_int(m));
    }
}

// ---------------- K2: pack strong/weak bitmasks (1 warp per row) ----------------
__global__ void k2_pack(const float* __restrict__ img) {
    int gw = (blockIdx.x * blockDim.x + threadIdx.x) >> 5;  // global warp = row
    int lane = threadIdx.x & 31;
    if (gw >= IMG_H) return;
    float mx = __int_as_float((int)d_maxbits);
    float high = mx * 0.15f;
    float low = high * 0.05f;

    const float4* rp = reinterpret_cast<const float4*>(img + (size_t)gw * IMG_W) + lane * 16;
    u64 sb = 0, wb = 0;
#pragma unroll
    for (int k = 0; k < 16; ++k) {
        float4 v = rp[k];
        int b = k * 4;
        sb |= ((u64)(v.x > high)) << (b + 0);
        sb |= ((u64)(v.y > high)) << (b + 1);
        sb |= ((u64)(v.z > high)) << (b + 2);
        sb |= ((u64)(v.w > high)) << (b + 3);
        wb |= ((u64)((v.x >= low) && (v.x <= high))) << (b + 0);
        wb |= ((u64)((v.y >= low) && (v.y <= high))) << (b + 1);
        wb |= ((u64)((v.z >= low) && (v.z <= high))) << (b + 2);
        wb |= ((u64)((v.w >= low) && (v.w <= high))) << (b + 3);
    }
    if (lane == 0)  wb &= ~1ull;              // column 0 not interior
    if (lane == 31) wb &= ~(1ull << 63);      // column W-1 not interior
    d_S[gw * NW + lane] = sb;
    d_W[gw * NW + lane] = wb;
}

// ---------------- K3: sequential hysteresis (single warp) ----------------
__global__ void __launch_bounds__(32, 1) k3_hyst() {
    const unsigned F = 0xffffffffu;
    const int l = threadIdx.x & 31;

    u64 ps = d_S[0 * NW + l];
    u64 cs = d_S[1 * NW + l];
    u64 ns = d_S[2 * NW + l];
    u64 w  = d_W[1 * NW + l];
    u64 ns2 = d_S[3 * NW + l];
    u64 w2  = d_W[2 * NW + l];

    // dilate(ps) across lane boundaries
    u64 psL = __shfl_up_sync(F, ps, 1);   if (l == 0)  psL = 0;
    u64 psR = __shfl_down_sync(F, ps, 1); if (l == 31) psR = 0;
    u64 nb = ps | ((ps << 1) | (psL >> 63)) | ((ps >> 1) | (psR << 63));

    // static base for row 1: shl(cs) | shr(ns)|ns|shl(ns)
    u64 csR = __shfl_down_sync(F, cs, 1); if (l == 31) csR = 0;
    u64 nsL = __shfl_up_sync(F, ns, 1);   if (l == 0)  nsL = 0;
    u64 nsR = __shfl_down_sync(F, ns, 1); if (l == 31) nsR = 0;
    u64 SB = ((cs >> 1) | (csR << 63)) | ((ns << 1) | (nsL >> 63)) | ns |
             ((ns >> 1) | (nsR << 63));

#pragma unroll 1
    for (int i = 1; i <= IMG_H - 2; ++i) {
        // prefetch two rows ahead (clamped indices)
        int si = (i + 3 < IMG_H) ? (i + 3) : (IMG_H - 1);
        int wi = (i + 2 < IMG_H - 1) ? (i + 2) : (IMG_H - 2);
        u64 nsP = d_S[si * NW + l];
        u64 wP  = d_W[wi * NW + l];

        // generate/propagate for this row
        u64 a = cs | (w & (SB | nb));
        u64 p = w & ~a;
        u64 x = a | w;

        // early shuffle of (a0,p0) for right-neighbor boundary bit
        unsigned low = (unsigned)(a & 1ull) | (((unsigned)(p & 1ull)) << 1);
        unsigned lowR = __shfl_down_sync(F, low, 1);
        if (l == 31) lowR = 0;

        u64 t1 = x + a;               // in-word carry chain, cin=0
        bool G = (t1 < x);            // word generate (carry out, cin=0)
        bool P = (p == ~0ull);        // word full-propagate
        unsigned Gm = __ballot_sync(F, G);
        unsigned Pm = __ballot_sync(F, P);

        // static base for next row (overlaps ballot latency)
        u64 csRn = __shfl_down_sync(F, ns, 1);  if (l == 31) csRn = 0;
        u64 nsLn = __shfl_up_sync(F, ns2, 1);   if (l == 0)  nsLn = 0;
        u64 nsRn = __shfl_down_sync(F, ns2, 1); if (l == 31) nsRn = 0;
        u64 SBn = ((ns >> 1) | (csRn << 63)) | ((ns2 << 1) | (nsLn >> 63)) |
                  ns2 | ((ns2 >> 1) | (nsRn << 63));

        // 32-bit cross-lane carry via adder trick
        unsigned x32 = Gm | Pm;
        unsigned cv32 = (x32 + Gm) ^ (x32 ^ Gm);   // bit l = carry into lane l
        u64 cin = (u64)((cv32 >> l) & 1u);

        u64 t2 = t1 + cin;
        u64 cv = t2 ^ x ^ a;                       // bit j = carry into bit j
        u64 co = (u64)G | (cin & (u64)(t1 == ~0ull));
        u64 s = (cv >> 1) | (co << 63);            // new-strong bits of this row
        d_So[i * NW + l] = s;

        // build dilate(s) for the next row without extra shuffles:
        // left boundary bit == this lane's cin; right boundary bit from (a0,p0,cinR)
        unsigned cinR = ((cv32 >> l) >> 1) & 1u;
        u64 rb = (u64)((lowR & 1u) | ((lowR >> 1) & cinR));
        nb = s | ((s << 1) | cin) | ((s >> 1) | (rb << 63));

        // rotate pipeline registers
        cs = ns; ns = ns2; w = w2;
        ns2 = nsP; w2 = wP; SB = SBn;
    }
}

// ---------------- K4: reconstruct float output ----------------
__global__ void k4_out(const float* __restrict__ img, float* __restrict__ out) {
    int idx = blockIdx.x * blockDim.x + threadIdx.x;   // one float4 per thread
    const int n4 = (IMG_H * IMG_W) / 4;
    if (idx >= n4) return;
    int row = idx >> 9;          // 512 float4 per row
    int c = (idx & 511) * 4;

    float mx = __int_as_float((int)d_maxbits);
    float high = mx * 0.15f;
    float low = high * 0.05f;

    float4 v = reinterpret_cast<const float4*>(img)[idx];
    float t0 = (v.x < low) ? 0.0f : ((v.x <= high) ? 25.0f : 255.0f);
    float t1 = (v.y < low) ? 0.0f : ((v.y <= high) ? 25.0f : 255.0f);
    float t2 = (v.z < low) ? 0.0f : ((v.z <= high) ? 25.0f : 255.0f);
    float t3 = (v.w < low) ? 0.0f : ((v.w <= high) ? 25.0f : 255.0f);

    float4 o;
    if (row == 0 || row == IMG_H - 1) {
        o.x = t0; o.y = t1; o.z = t2; o.w = t3;
    } else {
        u64 sw = d_So[row * NW + (c >> 6)];
        u64 ww = d_W [row * NW + (c >> 6)];
        int sh = c & 63;
        u64 sb = sw >> sh, wb = ww >> sh;
        o.x = (wb & 1ull) ? ((sb & 1ull) ? 255.0f : 0.0f) : t0;
        o.y = ((wb >> 1) & 1ull) ? (((sb >> 1) & 1ull) ? 255.0f : 0.0f) : t1;
        o.z = ((wb >> 2) & 1ull) ? (((sb >> 2) & 1ull) ? 255.0f : 0.0f) : t2;
        o.w = ((wb >> 3) & 1ull) ? (((sb >> 3) & 1ull) ? 255.0f : 0.0f) : t3;
    }
    reinterpret_cast<float4*>(out)[idx] = o;
}

extern "C" void kernel_launch(void* const* d_in, const int* in_sizes, int n_in,
                              void* d_out, int out_size) {
    const float* img = (const float*)d_in[0];
    float* out = (float*)d_out;
    (void)in_sizes; (void)n_in; (void)out_size;

    k0_reset<<<1, 1>>>();
    k1_max<<<256, 256>>>(img);
    k2_pack<<<IMG_H / 8, 256>>>(img);      // 8 warps per block, 1 warp per row
    k3_hyst<<<1, 32>>>();
    k4_out<<<(IMG_H * IMG_W / 4 + 255) / 256, 256>>>(img, out);
}

// round 4
// speedup vs baseline: 6.2568x; 6.2568x over previous
#include <cuda_runtime.h>
#include <cuda_bf16.h>
#include <cstdint>

// Image is 2048 x 2048 float32.
#define IMG_H 2048
#define IMG_W 2048
#define NW 32            // u64 words per row (2048 bits)
#define BANDS 32
#define WARM 24

typedef unsigned long long u64;

__device__ u64 d_S [IMG_H * NW];   // original strong bits (x > high)
__device__ u64 d_W [IMG_H * NW];   // weak bits (low<=x<=high) & interior-column
__device__ u64 d_So[IMG_H * NW];   // new strong bits after hysteresis (rows 1..2046)
__device__ u64 d_bnd[BANDS * NW];  // published TRUE boundary (last row's s of band k)
__device__ int d_flag[BANDS];
__device__ unsigned d_maxbits;

// ---------------- K0: reset ----------------
__global__ void k0_reset() {
    if (threadIdx.x == 0) d_maxbits = 0u;
    if (threadIdx.x < BANDS) d_flag[threadIdx.x] = 0;
}

// ---------------- K1: max reduction ----------------
__global__ void k1_max(const float* __restrict__ img) {
    const float4* p4 = reinterpret_cast<const float4*>(img);
    const int n4 = (IMG_H * IMG_W) / 4;
    float m = 0.0f;
    for (int i = blockIdx.x * blockDim.x + threadIdx.x; i < n4;
         i += gridDim.x * blockDim.x) {
        float4 v = p4[i];
        m = fmaxf(m, fmaxf(fmaxf(v.x, v.y), fmaxf(v.z, v.w)));
    }
    for (int o = 16; o > 0; o >>= 1)
        m = fmaxf(m, __shfl_xor_sync(0xffffffffu, m, o));
    __shared__ float sm[32];
    int lane = threadIdx.x & 31, wid = threadIdx.x >> 5;
    if (lane == 0) sm[wid] = m;
    __syncthreads();
    if (wid == 0) {
        int nwarp = blockDim.x >> 5;
        m = (lane < nwarp) ? sm[lane] : 0.0f;
        for (int o = 16; o > 0; o >>= 1)
            m = fmaxf(m, __shfl_xor_sync(0xffffffffu, m, o));
        if (lane == 0)
            atomicMax(reinterpret_cast<int*>(&d_maxbits), __float_as_int(m));
    }
}

// ---------------- K2: pack strong/weak bitmasks (1 warp per row) ----------------
__global__ void k2_pack(const float* __restrict__ img) {
    int gw = (blockIdx.x * blockDim.x + threadIdx.x) >> 5;  // global warp = row
    int lane = threadIdx.x & 31;
    if (gw >= IMG_H) return;
    float mx = __int_as_float((int)d_maxbits);
    float high = mx * 0.15f;
    float low = high * 0.05f;

    const float4* rp = reinterpret_cast<const float4*>(img + (size_t)gw * IMG_W) + lane * 16;
    u64 sb = 0, wb = 0;
#pragma unroll
    for (int k = 0; k < 16; ++k) {
        float4 v = rp[k];
        int b = k * 4;
        sb |= ((u64)(v.x > high)) << (b + 0);
        sb |= ((u64)(v.y > high)) << (b + 1);
        sb |= ((u64)(v.z > high)) << (b + 2);
        sb |= ((u64)(v.w > high)) << (b + 3);
        wb |= ((u64)((v.x >= low) && (v.x <= high))) << (b + 0);
        wb |= ((u64)((v.y >= low) && (v.y <= high))) << (b + 1);
        wb |= ((u64)((v.z >= low) && (v.z <= high))) << (b + 2);
        wb |= ((u64)((v.w >= low) && (v.w <= high))) << (b + 3);
    }
    if (lane == 0)  wb &= ~1ull;              // column 0 not interior
    if (lane == 31) wb &= ~(1ull << 63);      // column W-1 not interior
    d_S[gw * NW + lane] = sb;
    d_W[gw * NW + lane] = wb;
}

// ---------------- K3: band-parallel hysteresis with exact verification ----------------
__device__ __forceinline__ u64 dil(u64 s, int l) {
    const unsigned F = 0xffffffffu;
    u64 sl = __shfl_up_sync(F, s, 1);   if (l == 0)  sl = 0;
    u64 sr = __shfl_down_sync(F, s, 1); if (l == 31) sr = 0;
    return s | ((s << 1) | (sl >> 63)) | ((s >> 1) | (sr << 63));
}

// Process rows [ws, re); store d_So for rows in [rs, re); capture s at row rs-1
// into *specp (if non-null). Returns s of row re-1. nb = dilate of incoming state.
__device__ __forceinline__ u64 run_rows(int ws, int rs, int re, u64 nb, int l,
                                        u64* specp) {
    const unsigned F = 0xffffffffu;
    // 3-deep register pipeline: at iteration i we hold S[i..i+3], W[i..i+2].
    u64 cs  = d_S[(ws + 0) * NW + l];
    u64 ns  = d_S[(ws + 1) * NW + l];
    u64 ns2 = d_S[(ws + 2) * NW + l];
    u64 ns3 = d_S[(ws + 3) * NW + l];
    u64 w   = d_W[(ws + 0) * NW + l];
    u64 w2  = d_W[(ws + 1) * NW + l];
    u64 w3  = d_W[(ws + 2) * NW + l];

    // static base for row ws: shl(cs) | shr(ns)|ns|shl(ns)
    u64 csR = __shfl_down_sync(F, cs, 1); if (l == 31) csR = 0;
    u64 nsL = __shfl_up_sync(F, ns, 1);   if (l == 0)  nsL = 0;
    u64 nsR = __shfl_down_sync(F, ns, 1); if (l == 31) nsR = 0;
    u64 SB = ((cs >> 1) | (csR << 63)) | ((ns << 1) | (nsL >> 63)) | ns |
             ((ns >> 1) | (nsR << 63));

    u64 last = 0;
#pragma unroll 1
    for (int i = ws; i < re; ++i) {
        // prefetch three rows ahead (clamped indices)
        int si = i + 4; if (si > IMG_H - 1) si = IMG_H - 1;
        int wi = i + 3; if (wi > IMG_H - 2) wi = IMG_H - 2;
        u64 nsP = d_S[si * NW + l];
        u64 wP  = d_W[wi * NW + l];

        // generate/propagate for this row
        u64 a = cs | (w & (SB | nb));
        u64 p = w & ~a;
        u64 x = a | w;

        // early shuffle of (a0,p0) for right-neighbor boundary bit
        unsigned lo = (unsigned)(a & 1ull) | (((unsigned)(p & 1ull)) << 1);
        unsigned loR = __shfl_down_sync(F, lo, 1);
        if (l == 31) loR = 0;

        u64 t1 = x + a;               // in-word carry chain, cin=0
        bool G = (t1 < x);            // word generate
        bool P = (p == ~0ull);        // word full-propagate
        unsigned Gm = __ballot_sync(F, G);
        unsigned Pm = __ballot_sync(F, P);

        // static base for next row (overlaps ballot latency)
        u64 csRn = __shfl_down_sync(F, ns, 1);  if (l == 31) csRn = 0;
        u64 nsLn = __shfl_up_sync(F, ns2, 1);   if (l == 0)  nsLn = 0;
        u64 nsRn = __shfl_down_sync(F, ns2, 1); if (l == 31) nsRn = 0;
        u64 SBn = ((ns >> 1) | (csRn << 63)) | ((ns2 << 1) | (nsLn >> 63)) |
                  ns2 | ((ns2 >> 1) | (nsRn << 63));

        // 32-bit cross-lane carry via adder trick
        unsigned x32 = Gm | Pm;
        unsigned cv32 = (x32 + Gm) ^ (x32 ^ Gm);   // bit l = carry into lane l
        u64 cin = (u64)((cv32 >> l) & 1u);

        u64 t2 = t1 + cin;
        u64 cv = t2 ^ x ^ a;                       // bit j = carry into bit j
        u64 co = (u64)G | (cin & (u64)(t1 == ~0ull));
        u64 s = (cv >> 1) | (co << 63);            // new-strong bits of this row

        if (i >= rs) d_So[i * NW + l] = s;
        else if (specp && i == rs - 1) *specp = s;
        last = s;

        // dilate(s) for next row without extra shuffles
        unsigned cinR = ((cv32 >> l) >> 1) & 1u;
        u64 rb = (u64)((loR & 1u) | ((loR >> 1) & cinR));
        nb = s | ((s << 1) | cin) | ((s >> 1) | (rb << 63));

        // rotate pipeline registers
        cs = ns; ns = ns2; ns2 = ns3; w = w2; w2 = w3;
        ns3 = nsP; w3 = wP; SB = SBn;
    }
    return last;
}

__global__ void __launch_bounds__(32, 1) k3_hyst() {
    const unsigned F = 0xffffffffu;
    const int l = threadIdx.x;
    const int k = blockIdx.x;
    const int rs = 1 + (2046 * k) / BANDS;        // first row owned by this band
    const int re = 1 + (2046 * (k + 1)) / BANDS;  // one past last row owned

    if (k == 0) {
        // Exact from the start: incoming state is row 0's original strong bits.
        u64 s0 = d_S[0 * NW + l];
        u64 last = run_rows(rs, rs, re, dil(s0, l), l, nullptr);
        d_bnd[k * NW + l] = last;
        __threadfence();
        if (l == 0) atomicExch(&d_flag[k], 1);
    } else {
        // Speculative pass with warm-up seeded from original strong bits.
        int ws = rs - WARM;
        u64 seed = d_S[(ws - 1) * NW + l];
        u64 spec = 0;
        u64 last = run_rows(ws, rs, re, dil(seed, l), l, &spec);

        // Wait for predecessor's true boundary.
        if (l == 0) { while (atomicAdd(&d_flag[k - 1], 0) == 0) {} }
        __syncwarp();
        __threadfence();
        u64 tin = d_bnd[(k - 1) * NW + l];

        if (__ballot_sync(F, tin == spec) == F) {
            // Speculation verified exact: our band output is correct.
            d_bnd[k * NW + l] = last;
        } else {
            // Mismatch: recompute band exactly from the true incoming state.
            last = run_rows(rs, rs, re, dil(tin, l), l, nullptr);
            d_bnd[k * NW + l] = last;
        }
        __threadfence();
        if (l == 0) atomicExch(&d_flag[k], 1);
    }
}

// ---------------- K4: reconstruct float output ----------------
__global__ void k4_out(const float* __restrict__ img, float* __restrict__ out) {
    int idx = blockIdx.x * blockDim.x + threadIdx.x;   // one float4 per thread
    const int n4 = (IMG_H * IMG_W) / 4;
    if (idx >= n4) return;
    int row = idx >> 9;          // 512 float4 per row
    int c = (idx & 511) * 4;

    float mx = __int_as_float((int)d_maxbits);
    float high = mx * 0.15f;
    float low = high * 0.05f;

    float4 v = reinterpret_cast<const float4*>(img)[idx];
    float t0 = (v.x < low) ? 0.0f : ((v.x <= high) ? 25.0f : 255.0f);
    float t1 = (v.y < low) ? 0.0f : ((v.y <= high) ? 25.0f : 255.0f);
    float t2 = (v.z < low) ? 0.0f : ((v.z <= high) ? 25.0f : 255.0f);
    float t3 = (v.w < low) ? 0.0f : ((v.w <= high) ? 25.0f : 255.0f);

    float4 o;
    if (row == 0 || row == IMG_H - 1) {
        o.x = t0; o.y = t1; o.z = t2; o.w = t3;
    } else {
        u64 sw = d_So[row * NW + (c >> 6)];
        u64 ww = d_W [row * NW + (c >> 6)];
        int sh = c & 63;
        u64 sb = sw >> sh, wb = ww >> sh;
        o.x = (wb & 1ull) ? ((sb & 1ull) ? 255.0f : 0.0f) : t0;
        o.y = ((wb >> 1) & 1ull) ? (((sb >> 1) & 1ull) ? 255.0f : 0.0f) : t1;
        o.z = ((wb >> 2) & 1ull) ? (((sb >> 2) & 1ull) ? 255.0f : 0.0f) : t2;
        o.w = ((wb >> 3) & 1ull) ? (((sb >> 3) & 1ull) ? 255.0f : 0.0f) : t3;
    }
    reinterpret_cast<float4*>(out)[idx] = o;
}

extern "C" void kernel_launch(void* const* d_in, const int* in_sizes, int n_in,
                              void* d_out, int out_size) {
    const float* img = (const float*)d_in[0];
    float* out = (float*)d_out;
    (void)in_sizes; (void)n_in; (void)out_size;

    k0_reset<<<1, 32>>>();
    k1_max<<<256, 256>>>(img);
    k2_pack<<<IMG_H / 8, 256>>>(img);      // 8 warps per block, 1 warp per row
    k3_hyst<<<BANDS, 32>>>();
    k4_out<<<(IMG_H * IMG_W / 4 + 255) / 256, 256>>>(img, out);
}

// round 8
// speedup vs baseline: 10.9071x; 1.7432x over previous
#include <cuda_runtime.h>
#include <cuda_bf16.h>
#include <cstdint>

// Image is 2048 x 2048 float32.
#define IMG_H 2048
#define IMG_W 2048
#define NW 32            // u64 words per row (2048 bits)
#define BANDS 32
#define WARM 16

typedef unsigned long long u64;

__device__ u64 d_S [IMG_H * NW];   // original strong bits (x > high)
__device__ u64 d_W [IMG_H * NW];   // weak bits (low<=x<=high) & interior-column
__device__ u64 d_So[IMG_H * NW];   // new strong bits after hysteresis (rows 1..2046)
__device__ u64 d_bnd [BANDS * NW]; // speculative outgoing boundary of band k
__device__ u64 d_spec[BANDS * NW]; // speculative incoming boundary of band k
__device__ unsigned d_maxbits;

// ---------------- K0: reset ----------------
__global__ void k0_reset() { d_maxbits = 0u; }

// ---------------- K1: max reduction ----------------
__global__ void k1_max(const float* __restrict__ img) {
    const float4* p4 = reinterpret_cast<const float4*>(img);
    const int n4 = (IMG_H * IMG_W) / 4;
    float m = 0.0f;
    for (int i = blockIdx.x * blockDim.x + threadIdx.x; i < n4;
         i += gridDim.x * blockDim.x) {
        float4 v = p4[i];
        m = fmaxf(m, fmaxf(fmaxf(v.x, v.y), fmaxf(v.z, v.w)));
    }
    for (int o = 16; o > 0; o >>= 1)
        m = fmaxf(m, __shfl_xor_sync(0xffffffffu, m, o));
    __shared__ float sm[32];
    int lane = threadIdx.x & 31, wid = threadIdx.x >> 5;
    if (lane == 0) sm[wid] = m;
    __syncthreads();
    if (wid == 0) {
        int nwarp = blockDim.x >> 5;
        m = (lane < nwarp) ? sm[lane] : 0.0f;
        for (int o = 16; o > 0; o >>= 1)
            m = fmaxf(m, __shfl_xor_sync(0xffffffffu, m, o));
        if (lane == 0)
            atomicMax(reinterpret_cast<int*>(&d_maxbits), __float_as_int(m));
    }
}

// ---------------- K2: pack strong/weak bitmasks (1 warp per row) ----------------
__global__ void k2_pack(const float* __restrict__ img) {
    int gw = (blockIdx.x * blockDim.x + threadIdx.x) >> 5;  // global warp = row
    int lane = threadIdx.x & 31;
    if (gw >= IMG_H) return;
    float mx = __int_as_float((int)d_maxbits);
    float high = mx * 0.15f;
    float low = high * 0.05f;

    const float4* rp = reinterpret_cast<const float4*>(img + (size_t)gw * IMG_W) + lane * 16;
    u64 sb = 0, wb = 0;
#pragma unroll
    for (int k = 0; k < 16; ++k) {
        float4 v = rp[k];
        int b = k * 4;
        sb |= ((u64)(v.x > high)) << (b + 0);
        sb |= ((u64)(v.y > high)) << (b + 1);
        sb |= ((u64)(v.z > high)) << (b + 2);
        sb |= ((u64)(v.w > high)) << (b + 3);
        wb |= ((u64)((v.x >= low) && (v.x <= high))) << (b + 0);
        wb |= ((u64)((v.y >= low) && (v.y <= high))) << (b + 1);
        wb |= ((u64)((v.z >= low) && (v.z <= high))) << (b + 2);
        wb |= ((u64)((v.w >= low) && (v.w <= high))) << (b + 3);
    }
    if (lane == 0)  wb &= ~1ull;              // column 0 not interior
    if (lane == 31) wb &= ~(1ull << 63);      // column W-1 not interior
    d_S[gw * NW + lane] = sb;
    d_W[gw * NW + lane] = wb;
}

// ---------------- hysteresis core ----------------
__device__ __forceinline__ u64 dil(u64 s, int l) {
    const unsigned F = 0xffffffffu;
    u64 sl = __shfl_up_sync(F, s, 1);   if (l == 0)  sl = 0;
    u64 sr = __shfl_down_sync(F, s, 1); if (l == 31) sr = 0;
    return s | ((s << 1) | (sl >> 63)) | ((s >> 1) | (sr << 63));
}

// Process rows [ws, re); store d_So for rows in [rs, re); capture s at row rs-1
// into *specp (if non-null). Returns s of row re-1. nb = dilate of incoming state.
__device__ __forceinline__ u64 run_rows(int ws, int rs, int re, u64 nb, int l,
                                        u64* specp) {
    const unsigned F = 0xffffffffu;
    // 3-deep register pipeline: at iteration i we hold S[i..i+3], W[i..i+2].
    u64 cs  = d_S[(ws + 0) * NW + l];
    u64 ns  = d_S[(ws + 1) * NW + l];
    u64 ns2 = d_S[(ws + 2) * NW + l];
    u64 ns3 = d_S[(ws + 3) * NW + l];
    u64 w   = d_W[(ws + 0) * NW + l];
    u64 w2  = d_W[(ws + 1) * NW + l];
    u64 w3  = d_W[(ws + 2) * NW + l];

    // static base for row ws: shl(cs) | shr(ns)|ns|shl(ns)
    u64 csR = __shfl_down_sync(F, cs, 1); if (l == 31) csR = 0;
    u64 nsL = __shfl_up_sync(F, ns, 1);   if (l == 0)  nsL = 0;
    u64 nsR = __shfl_down_sync(F, ns, 1); if (l == 31) nsR = 0;
    u64 SB = ((cs >> 1) | (csR << 63)) | ((ns << 1) | (nsL >> 63)) | ns |
             ((ns >> 1) | (nsR << 63));

    u64 last = 0;
#pragma unroll 1
    for (int i = ws; i < re; ++i) {
        // prefetch three rows ahead (clamped indices)
        int si = i + 4; if (si > IMG_H - 1) si = IMG_H - 1;
        int wi = i + 3; if (wi > IMG_H - 2) wi = IMG_H - 2;
        u64 nsP = d_S[si * NW + l];
        u64 wP  = d_W[wi * NW + l];

        // generate/propagate for this row
        u64 a = cs | (w & (SB | nb));
        u64 p = w & ~a;
        u64 x = a | w;

        // early shuffle of (a0,p0) for right-neighbor boundary bit
        unsigned lo = (unsigned)(a & 1ull) | (((unsigned)(p & 1ull)) << 1);
        unsigned loR = __shfl_down_sync(F, lo, 1);
        if (l == 31) loR = 0;

        u64 t1 = x + a;               // in-word carry chain, cin=0
        bool G = (t1 < x);            // word generate
        bool P = (p == ~0ull);        // word full-propagate
        unsigned Gm = __ballot_sync(F, G);
        unsigned Pm = __ballot_sync(F, P);

        // static base for next row (overlaps ballot latency)
        u64 csRn = __shfl_down_sync(F, ns, 1);  if (l == 31) csRn = 0;
        u64 nsLn = __shfl_up_sync(F, ns2, 1);   if (l == 0)  nsLn = 0;
        u64 nsRn = __shfl_down_sync(F, ns2, 1); if (l == 31) nsRn = 0;
        u64 SBn = ((ns >> 1) | (csRn << 63)) | ((ns2 << 1) | (nsLn >> 63)) |
                  ns2 | ((ns2 >> 1) | (nsRn << 63));

        // 32-bit cross-lane carry via adder trick
        unsigned x32 = Gm | Pm;
        unsigned cv32 = (x32 + Gm) ^ (x32 ^ Gm);   // bit l = carry into lane l
        u64 cin = (u64)((cv32 >> l) & 1u);

        u64 t2 = t1 + cin;
        u64 cv = t2 ^ x ^ a;                       // bit j = carry into bit j
        u64 co = (u64)G | (cin & (u64)(t1 == ~0ull));
        u64 s = (cv >> 1) | (co << 63);            // new-strong bits of this row

        if (i >= rs) d_So[i * NW + l] = s;
        else if (specp && i == rs - 1) *specp = s;
        last = s;

        // dilate(s) for next row without extra shuffles
        unsigned cinR = ((cv32 >> l) >> 1) & 1u;
        u64 rb = (u64)((loR & 1u) | ((loR >> 1) & cinR));
        nb = s | ((s << 1) | cin) | ((s >> 1) | (rb << 63));

        // rotate pipeline registers
        cs = ns; ns = ns2; ns2 = ns3; w = w2; w2 = w3;
        ns3 = nsP; w3 = wP; SB = SBn;
    }
    return last;
}

// ---------------- K3a: band-parallel speculative hysteresis (no sync) ----------------
__global__ void __launch_bounds__(32, 1) k3a_spec() {
    const int l = threadIdx.x;
    const int k = blockIdx.x;
    const int rs = 1 + (2046 * k) / BANDS;
    const int re = 1 + (2046 * (k + 1)) / BANDS;

    if (k == 0) {
        // Exact from the start: incoming state is row 0's original strong bits.
        u64 s0 = d_S[0 * NW + l];
        u64 last = run_rows(rs, rs, re, dil(s0, l), l, nullptr);
        d_bnd[0 * NW + l] = last;
    } else {
        int ws = rs - WARM;
        u64 seed = d_S[(ws - 1) * NW + l];
        u64 spec = 0;
        u64 last = run_rows(ws, rs, re, dil(seed, l), l, &spec);
        d_spec[k * NW + l] = spec;
        d_bnd[k * NW + l] = last;
    }
}

// ---------------- K3b: verify; sequential in-block fixup if needed ----------------
__global__ void __launch_bounds__(BANDS * 32, 1) k3b_fix() {
    const unsigned F = 0xffffffffu;
    __shared__ u64 tout[BANDS * 32];
    __shared__ int wmatch[BANDS];
    __shared__ int allm;
    const int l = threadIdx.x & 31;
    const int k = threadIdx.x >> 5;   // band handled by this warp

    int m = 1;
    if (k > 0) {
        u64 spec = d_spec[k * NW + l];
        u64 po = d_bnd[(k - 1) * NW + l];
        m = (__ballot_sync(F, spec == po) == F) ? 1 : 0;
    }
    if (l == 0) wmatch[k] = m;
    __syncthreads();
    if (threadIdx.x == 0) {
        int a = 1;
#pragma unroll
        for (int i = 0; i < BANDS; ++i) a &= wmatch[i];
        allm = a;
    }
    __syncthreads();
    if (allm) return;   // expected case: all speculation verified exact

    // Sequential fixup with cheap smem hand-off. Exactness: if the true
    // incoming boundary equals the speculated one, the band's d_So rows and
    // outgoing boundary are already correct; otherwise recompute from truth.
    for (int step = 0; step < BANDS; ++step) {
        if (k == step) {
            if (k == 0) {
                tout[0 * 32 + l] = d_bnd[0 * NW + l];
            } else {
                const int rs = 1 + (2046 * k) / BANDS;
                const int re = 1 + (2046 * (k + 1)) / BANDS;
                u64 tin = tout[(k - 1) * 32 + l];
                u64 spec = d_spec[k * NW + l];
                if (__ballot_sync(F, tin == spec) == F) {
                    tout[k * 32 + l] = d_bnd[k * NW + l];
                } else {
                    u64 last = run_rows(rs, rs, re, dil(tin, l), l, nullptr);
                    tout[k * 32 + l] = last;
                }
            }
        }
        __syncthreads();
    }
}

// ---------------- K4: reconstruct float output ----------------
__global__ void k4_out(const float* __restrict__ img, float* __restrict__ out) {
    int idx = blockIdx.x * blockDim.x + threadIdx.x;   // one float4 per thread
    const int n4 = (IMG_H * IMG_W) / 4;
    if (idx >= n4) return;
    int row = idx >> 9;          // 512 float4 per row
    int c = (idx & 511) * 4;

    float mx = __int_as_float((int)d_maxbits);
    float high = mx * 0.15f;
    float low = high * 0.05f;

    float4 v = reinterpret_cast<const float4*>(img)[idx];
    float t0 = (v.x < low) ? 0.0f : ((v.x <= high) ? 25.0f : 255.0f);
    float t1 = (v.y < low) ? 0.0f : ((v.y <= high) ? 25.0f : 255.0f);
    float t2 = (v.z < low) ? 0.0f : ((v.z <= high) ? 25.0f : 255.0f);
    float t3 = (v.w < low) ? 0.0f : ((v.w <= high) ? 25.0f : 255.0f);

    float4 o;
    if (row == 0 || row == IMG_H - 1) {
        o.x = t0; o.y = t1; o.z = t2; o.w = t3;
    } else {
        u64 sw = d_So[row * NW + (c >> 6)];
        u64 ww = d_W [row * NW + (c >> 6)];
        int sh = c & 63;
        u64 sb = sw >> sh, wb = ww >> sh;
        o.x = (wb & 1ull) ? ((sb & 1ull) ? 255.0f : 0.0f) : t0;
        o.y = ((wb >> 1) & 1ull) ? (((sb >> 1) & 1ull) ? 255.0f : 0.0f) : t1;
        o.z = ((wb >> 2) & 1ull) ? (((sb >> 2) & 1ull) ? 255.0f : 0.0f) : t2;
        o.w = ((wb >> 3) & 1ull) ? (((sb >> 3) & 1ull) ? 255.0f : 0.0f) : t3;
    }
    reinterpret_cast<float4*>(out)[idx] = o;
}

extern "C" void kernel_launch(void* const* d_in, const int* in_sizes, int n_in,
                              void* d_out, int out_size) {
    const float* img = (const float*)d_in[0];
    float* out = (float*)d_out;
    (void)in_sizes; (void)n_in; (void)out_size;

    k0_reset<<<1, 1>>>();
    k1_max<<<256, 256>>>(img);
    k2_pack<<<IMG_H / 8, 256>>>(img);      // 8 warps per block, 1 warp per row
    k3a_spec<<<BANDS, 32>>>();
    k3b_fix<<<1, BANDS * 32>>>();
    k4_out<<<(IMG_H * IMG_W / 4 + 255) / 256, 256>>>(img, out);
}